// round 6
// baseline (speedup 1.0000x reference)
#include <cuda_runtime.h>
#include <cuda_bf16.h>

// Rotation scan: h_t = lambda * h_{t-1} + x_t  (complex), lambda = r*cos(th) - i*r*sin(th)
// x: (T, N, 2) fp32 -> float2[T][N]. Output same shape.
//
// R6: R1 memory shape (NB=16 n-columns/CTA, grid=512, 128B warp segments,
// L=16 steps/thread) with minimized synchronization:
//  - TT 8->16, THREADS 128->256: 256 timesteps per super-iteration
//  - double-buffered sagg: ONE __syncthreads per super-iteration
//  => 16 barriers total vs R1's 64. No prefetch (R5's regression), no float4
//  (R4's regression). Streaming hint on stores only.

#define L  16
#define TT 16
#define NB 16
#define THREADS (TT * NB)   // 256

__global__ void __launch_bounds__(THREADS)
rot_scan_kernel(const float2* __restrict__ x,
                const float*  __restrict__ angles,
                const float*  __restrict__ rets,
                float2* __restrict__ out,
                int T, int N)
{
    const int tid     = threadIdx.x;
    const int n_local = tid & (NB - 1);   // n fastest -> warp = 2 t x 16 n, 2x128B
    const int tt      = tid / NB;         // 0..TT-1
    const int n       = blockIdx.x * NB + n_local;

    // ---- per-n operator: lambda = ret*cos(ang) - i*ret*sin(ang) ----
    const float PI = 3.14159265358979323846f;
    float ang = (tanhf(angles[n]) + 1.0f) * 0.5f * PI;   // (0, pi)
    float ret = (tanhf(rets[n])   + 1.0f) * 0.5f;        // (0, 1)
    float sn, cs;
    sincosf(ang, &sn, &cs);
    const float lr =  ret * cs;
    const float li = -ret * sn;

    // lambda^L (L=16): 4 complex squarings
    float plr = lr, pli = li;
#pragma unroll
    for (int q = 0; q < 4; q++) {
        float nr = plr * plr - pli * pli;
        float ni = 2.0f * plr * pli;
        plr = nr; pli = ni;
    }
    // lambda^(L*tt): thread-specific weight for block-carry
    float wr = 1.0f, wi = 0.0f;
    for (int j = 0; j < tt; j++) {
        float nr = wr * plr - wi * pli;
        float ni = wr * pli + wi * plr;
        wr = nr; wi = ni;
    }
    // lambda^(L*TT) = (lambda^L)^16: 4 squarings
    float flr = plr, fli = pli;
#pragma unroll
    for (int q = 0; q < 4; q++) {
        float nr = flr * flr - fli * fli;
        float ni = 2.0f * flr * fli;
        flr = nr; fli = ni;
    }

    __shared__ float2 sagg[2][TT][NB];   // double buffer -> 1 barrier/iter

    float hpr = 0.0f, hpi = 0.0f;   // running carry: h before this super-iteration

    float2 v[L];

    const int steps  = L * TT;       // 256
    const int n_iter = T / steps;    // 16

    for (int it = 0; it < n_iter; it++) {
        const int buf = it & 1;
        const int t0  = it * steps + tt * L;
        const float2* xp = x + (size_t)t0 * N + n;

        // load + local scan (zero-initialized); ptxas schedules loads
        float br = 0.0f, bi = 0.0f;
#pragma unroll
        for (int i = 0; i < L; i++) {
            float2 xv = xp[(size_t)i * N];
            float nr = fmaf(lr, br, fmaf(-li, bi, xv.x));
            float ni = fmaf(lr, bi, fmaf( li, br, xv.y));
            br = nr; bi = ni;
            v[i].x = br; v[i].y = bi;
        }
        sagg[buf][tt][n_local] = make_float2(br, bi);
        __syncthreads();
        // Safety of single barrier: writes to buffer b at iteration it+2 are
        // ordered after barrier(it+1), which is after every thread finished
        // reading buffer b in combine(it). Buffers alternate per iteration.

        // combine aggregates: acc_j = lambda^L * acc_{j-1} + A_j
        // carry for this thread = acc just before adding A_tt (i.e. I_{tt-1})
        float accr = 0.0f, acci = 0.0f;
        float carr = 0.0f, cari = 0.0f;
#pragma unroll
        for (int j = 0; j < TT; j++) {
            if (j == tt) { carr = accr; cari = acci; }
            float2 a = sagg[buf][j][n_local];
            float nr = fmaf(plr, accr, fmaf(-pli, acci, a.x));
            float ni = fmaf(plr, acci, fmaf( pli, accr, a.y));
            accr = nr; acci = ni;
        }

        // total carry-in for this thread = lambda^(L*tt) * h_prev + I_{tt-1}
        float cr = fmaf(wr, hpr, fmaf(-wi, hpi, carr));
        float ci = fmaf(wr, hpi, fmaf( wi, hpr, cari));

        // outputs: out_i = v_i + lambda^(i+1) * carry
        float2* op = out + (size_t)t0 * N + n;
        float qr = fmaf(lr, cr, -li * ci);
        float qi = fmaf(lr, ci,  li * cr);
#pragma unroll
        for (int i = 0; i < L; i++) {
            float2 o;
            o.x = v[i].x + qr;
            o.y = v[i].y + qi;
            __stcs(op + (size_t)i * N, o);
            float nr = fmaf(lr, qr, -li * qi);
            float ni = fmaf(lr, qi,  li * qr);
            qr = nr; qi = ni;
        }

        // advance block carry: h_prev = lambda^(L*TT) * h_prev + I_{TT-1}
        float nhr = fmaf(flr, hpr, fmaf(-fli, hpi, accr));
        float nhi = fmaf(flr, hpi, fmaf( fli, hpr, acci));
        hpr = nhr; hpi = nhi;
    }
}

extern "C" void kernel_launch(void* const* d_in, const int* in_sizes, int n_in,
                              void* d_out, int out_size)
{
    const float2* x    = (const float2*)d_in[0];
    const float*  angs = (const float*)d_in[1];
    const float*  rts  = (const float*)d_in[2];
    float2* out = (float2*)d_out;

    const int N = in_sizes[1];                       // 8192
    const int T = in_sizes[0] / (2 * N);             // 4096

    const int grid = N / NB;                         // 512 blocks
    rot_scan_kernel<<<grid, THREADS>>>(x, angs, rts, out, T, N);
}

// round 7
// speedup vs baseline: 1.0908x; 1.0908x over previous
#include <cuda_runtime.h>
#include <cuda_bf16.h>

// Rotation scan: h_t = lambda * h_{t-1} + x_t  (complex), lambda = r*cos(th) - i*r*sin(th)
// x: (T, N, 2) fp32 -> float2[T][N]. Output same shape.
//
// R7 = R1 champion config exactly (block=128, NB=16, TT=8, L=16, grid=512,
// PLAIN loads + stores — both stcs rounds drew worse wall at equal kernel
// time), plus the one safe improvement: double-buffered sagg -> one
// __syncthreads per 128-step super-iteration (32 barriers vs 64).
// Six-round evidence: ~5.8 TB/s is the HBM ceiling for this 1:1 r/w fp32
// stream; all pressure/width/occupancy levers are exhausted.

#define L  16
#define TT 8
#define NB 16
#define THREADS (TT * NB)   // 128

__global__ void __launch_bounds__(THREADS)
rot_scan_kernel(const float2* __restrict__ x,
                const float*  __restrict__ angles,
                const float*  __restrict__ rets,
                float2* __restrict__ out,
                int T, int N)
{
    const int tid     = threadIdx.x;
    const int n_local = tid & (NB - 1);   // n fastest -> coalesced gmem
    const int tt      = tid / NB;         // 0..TT-1
    const int n       = blockIdx.x * NB + n_local;

    // ---- per-n operator: lambda = ret*cos(ang) - i*ret*sin(ang) ----
    const float PI = 3.14159265358979323846f;
    float ang = (tanhf(angles[n]) + 1.0f) * 0.5f * PI;   // (0, pi)
    float ret = (tanhf(rets[n])   + 1.0f) * 0.5f;        // (0, 1)
    float sn, cs;
    sincosf(ang, &sn, &cs);
    const float lr =  ret * cs;
    const float li = -ret * sn;

    // lambda^L (L=16): 4 complex squarings
    float plr = lr, pli = li;
#pragma unroll
    for (int q = 0; q < 4; q++) {
        float nr = plr * plr - pli * pli;
        float ni = 2.0f * plr * pli;
        plr = nr; pli = ni;
    }
    // lambda^(L*tt): thread-specific weight for block-carry
    float wr = 1.0f, wi = 0.0f;
    for (int j = 0; j < tt; j++) {
        float nr = wr * plr - wi * pli;
        float ni = wr * pli + wi * plr;
        wr = nr; wi = ni;
    }
    // lambda^(L*TT) = (lambda^L)^8: 3 squarings
    float flr = plr, fli = pli;
#pragma unroll
    for (int q = 0; q < 3; q++) {
        float nr = flr * flr - fli * fli;
        float ni = 2.0f * flr * fli;
        flr = nr; fli = ni;
    }

    __shared__ float2 sagg[2][TT][NB];   // double buffer -> 1 barrier/iter

    float hpr = 0.0f, hpi = 0.0f;   // running carry: h before this super-iteration

    float2 v[L];

    const int steps  = L * TT;       // 128
    const int n_iter = T / steps;    // 32

    for (int it = 0; it < n_iter; it++) {
        const int buf = it & 1;
        const int t0  = it * steps + tt * L;
        const float2* xp = x + (size_t)t0 * N + n;

        // load + local scan (zero-initialized)
        float br = 0.0f, bi = 0.0f;
#pragma unroll
        for (int i = 0; i < L; i++) {
            float2 xv = xp[(size_t)i * N];
            float nr = fmaf(lr, br, fmaf(-li, bi, xv.x));
            float ni = fmaf(lr, bi, fmaf( li, br, xv.y));
            br = nr; bi = ni;
            v[i].x = br; v[i].y = bi;
        }
        sagg[buf][tt][n_local] = make_float2(br, bi);
        __syncthreads();
        // Single-barrier safety: iteration it+2's writes to buffer `buf` are
        // ordered after barrier(it+1), which is after every thread finished
        // reading buffer `buf` in combine(it). Buffers alternate per iteration.

        // combine aggregates: acc_j = lambda^L * acc_{j-1} + A_j
        // carry for this thread = acc just before adding A_tt (i.e. I_{tt-1})
        float accr = 0.0f, acci = 0.0f;
        float carr = 0.0f, cari = 0.0f;
#pragma unroll
        for (int j = 0; j < TT; j++) {
            if (j == tt) { carr = accr; cari = acci; }
            float2 a = sagg[buf][j][n_local];
            float nr = fmaf(plr, accr, fmaf(-pli, acci, a.x));
            float ni = fmaf(plr, acci, fmaf( pli, accr, a.y));
            accr = nr; acci = ni;
        }

        // total carry-in for this thread = lambda^(L*tt) * h_prev + I_{tt-1}
        float cr = fmaf(wr, hpr, fmaf(-wi, hpi, carr));
        float ci = fmaf(wr, hpi, fmaf( wi, hpr, cari));

        // outputs: out_i = v_i + lambda^(i+1) * carry
        float2* op = out + (size_t)t0 * N + n;
        float qr = fmaf(lr, cr, -li * ci);
        float qi = fmaf(lr, ci,  li * cr);
#pragma unroll
        for (int i = 0; i < L; i++) {
            float2 o;
            o.x = v[i].x + qr;
            o.y = v[i].y + qi;
            op[(size_t)i * N] = o;
            float nr = fmaf(lr, qr, -li * qi);
            float ni = fmaf(lr, qi,  li * qr);
            qr = nr; qi = ni;
        }

        // advance block carry: h_prev = lambda^(L*TT) * h_prev + I_{TT-1}
        float nhr = fmaf(flr, hpr, fmaf(-fli, hpi, accr));
        float nhi = fmaf(flr, hpi, fmaf( fli, hpr, acci));
        hpr = nhr; hpi = nhi;
    }
}

extern "C" void kernel_launch(void* const* d_in, const int* in_sizes, int n_in,
                              void* d_out, int out_size)
{
    const float2* x    = (const float2*)d_in[0];
    const float*  angs = (const float*)d_in[1];
    const float*  rts  = (const float*)d_in[2];
    float2* out = (float2*)d_out;

    const int N = in_sizes[1];                       // 8192
    const int T = in_sizes[0] / (2 * N);             // 4096

    const int grid = N / NB;                         // 512 blocks
    rot_scan_kernel<<<grid, THREADS>>>(x, angs, rts, out, T, N);
}